// round 17
// baseline (speedup 1.0000x reference)
#include <cuda_runtime.h>
#include <cuda_fp16.h>
#include <cstdint>

#define N_NODES 100000
#define N_EDGES 3200000
#define BATCH   16
#define HIDDEN  64
#define NBANK   4                      // accumulation banks (calibrated err ~6.1e-4)

// Lookup table for the scalar MLP f(x): 1 -> 64 GELU(erf) -> 1
#define TBL_N     16384
#define TBL_RANGE 10.0f
#define TBL_SCALE ((float)TBL_N / (2.0f * TBL_RANGE))
#define TBL_OFF   ((float)TBL_N * 0.5f)

#define TBL_BLOCKS  ((TBL_N + 1 + 255) / 256)            // 65
#define PREP_BLOCKS ((N_NODES * 4 + 255) / 256)          // 1563 (4 threads/node)

// Scratch (device globals; zero-initialized at module load).
// INVARIANT: g_agg16 (all banks) and g_deg are all-zero at kernel_launch
// entry — loader zero-init on first call; mlp_kernel consume-and-reset after.
// g_agg16 is BANK-major: [bank][node][16 halves] -> coalesced merge streams.
__device__ __align__(16) unsigned g_muT16[(size_t)N_NODES * 8];          // mu fp16 [N][16]
__device__ __align__(16) unsigned g_agg16[(size_t)NBANK * N_NODES * 8];  // fp16 acc banks
__device__ float                  g_deg[N_NODES];                        // exact f32 degrees
__device__ float                  g_tbl[TBL_N + 2];                      // f(x) samples

// ---------------------------------------------------------------------------
// Exact scalar MLP (erf GELU) — table build + rare out-of-range fallback.
// ---------------------------------------------------------------------------
__device__ __forceinline__ float mlp_exact(float x,
                                           const float* __restrict__ W1,
                                           const float* __restrict__ b1,
                                           const float* __restrict__ W2,
                                           const float* __restrict__ b2) {
    float acc = b2[0];
    #pragma unroll 8
    for (int h = 0; h < HIDDEN; h++) {
        const float z = fmaf(x, __ldg(W1 + h), __ldg(b1 + h));
        const float g = 0.5f * z * (1.0f + erff(z * 0.70710678118654752440f));
        acc = fmaf(g, __ldg(W2 + h), acc);
    }
    return acc;
}

__device__ __forceinline__ float lut_eval(float x,
                                          const float* __restrict__ W1,
                                          const float* __restrict__ b1,
                                          const float* __restrict__ W2,
                                          const float* __restrict__ b2) {
    const float u = fmaf(x, TBL_SCALE, TBL_OFF);
    if (u >= 0.0f && u < (float)TBL_N) {
        const int   i    = (int)u;
        const float frac = u - (float)i;
        const float t0 = __ldg(g_tbl + i);
        const float t1 = __ldg(g_tbl + i + 1);
        return fmaf(t1 - t0, frac, t0);
    }
    return mlp_exact(x, W1, b1, W2, b2);   // |x| > 10: essentially never
}

// ---------------------------------------------------------------------------
// Kernel A1 (merged, 2 block ranges): LUT build + mu transpose to fp16.
// Runs on stream A, CONCURRENT with deg_kernel on stream B (disjoint data).
// ---------------------------------------------------------------------------
__global__ void __launch_bounds__(256) init_kernel(const float* __restrict__ mu,
                                                   const float* __restrict__ W1,
                                                   const float* __restrict__ b1,
                                                   const float* __restrict__ W2,
                                                   const float* __restrict__ b2) {
    if (blockIdx.x < TBL_BLOCKS) {
        const int i = blockIdx.x * 256 + threadIdx.x;
        if (i <= TBL_N) {
            const float x = -TBL_RANGE + (2.0f * TBL_RANGE / (float)TBL_N) * (float)i;
            g_tbl[i] = mlp_exact(x, W1, b1, W2, b2);
        }
        return;
    }

    const int idx  = (blockIdx.x - TBL_BLOCKS) * 256 + threadIdx.x;
    const int n    = idx >> 2;          // node
    const int part = idx & 3;           // which 4-batch slice
    if (n >= N_NODES) return;

    const int b0 = part * 4;
    float v0 = __ldg(mu + (size_t)(b0 + 0) * N_NODES + n);
    float v1 = __ldg(mu + (size_t)(b0 + 1) * N_NODES + n);
    float v2 = __ldg(mu + (size_t)(b0 + 2) * N_NODES + n);
    float v3 = __ldg(mu + (size_t)(b0 + 3) * N_NODES + n);

    const __half2 p0 = __float22half2_rn(make_float2(v0, v1));
    const __half2 p1 = __float22half2_rn(make_float2(v2, v3));
    uint2 w;
    w.x = *reinterpret_cast<const unsigned*>(&p0);
    w.y = *reinterpret_cast<const unsigned*>(&p1);
    *reinterpret_cast<uint2*>(g_muT16 + (size_t)n * 8 + part * 2) = w;
}

// ---------------------------------------------------------------------------
// Kernel B1 (stream B): degree histogram, 4 edges/thread via int4.
// Depends only on ei — overlaps with init_kernel (SM-bound, LTS-idle).
// ---------------------------------------------------------------------------
__global__ void __launch_bounds__(256) deg_kernel(const int* __restrict__ ei) {
    const int i4 = blockIdx.x * blockDim.x + threadIdx.x;
    if (i4 >= N_EDGES / 4) return;
    const int4 rr = __ldg(reinterpret_cast<const int4*>(ei) + i4);
    #pragma unroll
    for (int k = 0; k < 4; k++) {
        const int r = (k == 0) ? rr.x : (k == 1) ? rr.y : (k == 2) ? rr.z : rr.w;
        if ((unsigned)r < N_NODES) {
            asm volatile("red.global.add.f32 [%0], %1;"
                         :: "l"(__cvta_generic_to_global(g_deg + r)), "f"(1.0f)
                         : "memory");
        }
    }
}

// ---------------------------------------------------------------------------
// Kernel A2: per-edge payload scatter, 2 lanes per edge (16 edges per warp).
// Each lane moves 16B (8 fp16 batches) with ONE red.global.add.noftz.v4.f16x2
// into bank (e & 3). Pure payload now — deg lives on stream B.
// ---------------------------------------------------------------------------
__global__ void __launch_bounds__(256) edge_kernel(const int* __restrict__ ei) {
    const int T = blockIdx.x * blockDim.x + threadIdx.x;
    const int e = T >> 1;        // edge id
    const int q = T & 1;         // which 16B half of the 32B row
    if (e >= N_EDGES) return;

    const int r = __ldg(ei + e);             // destination (row)
    const int c = __ldg(ei + N_EDGES + e);   // source (col)
    if ((unsigned)r >= N_NODES || (unsigned)c >= N_NODES) return;

    const uint4 v = *reinterpret_cast<const uint4*>(g_muT16 + (size_t)c * 8 + q * 4);
    unsigned* dst = g_agg16 + ((size_t)(e & (NBANK - 1)) * N_NODES + r) * 8 + q * 4;
    asm volatile("red.global.add.noftz.v4.f16x2 [%0], {%1, %2, %3, %4};"
                 :: "l"(__cvta_generic_to_global(dst)),
                    "r"(v.x), "r"(v.y), "r"(v.z), "r"(v.w)
                 : "memory");
}

// ---------------------------------------------------------------------------
// Kernel A3: merge the 4 fp16 banks in f32, mean, LUT MLP, staged coalesced
// write-out. One thread = one node: 8 independent uint4 loads in flight,
// thread-private deg read+reset. CONSUME-AND-RESET for the next replay.
// ---------------------------------------------------------------------------
__global__ void __launch_bounds__(256) mlp_kernel(const float* __restrict__ W1,
                                                  const float* __restrict__ b1,
                                                  const float* __restrict__ W2,
                                                  const float* __restrict__ b2,
                                                  float* __restrict__ out) {
    __shared__ float tileY[BATCH][256 + 4];

    const int t  = threadIdx.x;
    const int n0 = blockIdx.x * 256;
    const int n  = n0 + t;

    float y[BATCH];
    #pragma unroll
    for (int k = 0; k < BATCH; k++) y[k] = 0.0f;

    if (n < N_NODES) {
        const float dg = g_deg[n];
        g_deg[n] = 0.0f;                           // thread-private reset

        uint4 a[NBANK][2];
        #pragma unroll
        for (int bk = 0; bk < NBANK; bk++) {
            uint4* ap = reinterpret_cast<uint4*>(
                g_agg16 + ((size_t)bk * N_NODES + n) * 8);
            a[bk][0] = ap[0];
            a[bk][1] = ap[1];
        }
        const uint4 z4 = make_uint4(0u, 0u, 0u, 0u);
        #pragma unroll
        for (int bk = 0; bk < NBANK; bk++) {
            uint4* ap = reinterpret_cast<uint4*>(
                g_agg16 + ((size_t)bk * N_NODES + n) * 8);
            ap[0] = z4;                            // reset for next replay
            ap[1] = z4;
        }

        float s[BATCH];
        #pragma unroll
        for (int k = 0; k < BATCH; k++) s[k] = 0.0f;
        #pragma unroll
        for (int bk = 0; bk < NBANK; bk++) {
            #pragma unroll
            for (int h = 0; h < 2; h++) {
                unsigned w[4] = {a[bk][h].x, a[bk][h].y, a[bk][h].z, a[bk][h].w};
                #pragma unroll
                for (int k = 0; k < 4; k++) {
                    const float2 f =
                        __half22float2(*reinterpret_cast<const __half2*>(&w[k]));
                    s[h * 8 + 2 * k + 0] += f.x;
                    s[h * 8 + 2 * k + 1] += f.y;
                }
            }
        }

        const float invd = 1.0f / fmaxf(dg, 1.0f);
        #pragma unroll
        for (int k = 0; k < BATCH; k++)
            y[k] = lut_eval(s[k] * invd, W1, b1, W2, b2);
    }

    #pragma unroll
    for (int k = 0; k < BATCH; k++)
        tileY[k][t] = y[k];
    __syncthreads();

    #pragma unroll
    for (int b = 0; b < BATCH; b++) {
        const int nn = n0 + t;
        if (nn < N_NODES) out[(size_t)b * N_NODES + nn] = tileY[b][t];
    }
}

// ---------------------------------------------------------------------------
// Fork-join schedule (graph-capturable cross-stream dependencies):
//   stream 0 : init ──────────── edge(payload) ──┬─ mlp
//   stream B : deg (only needs ei) ─────────────-┘
// ---------------------------------------------------------------------------
extern "C" void kernel_launch(void* const* d_in, const int* in_sizes, int n_in,
                              void* d_out, int out_size) {
    const float* mu = (const float*)d_in[0];
    const int*   ei = (const int*)d_in[1];     // edge_index stored as int32
    const float* W1 = (const float*)d_in[2];
    const float* b1 = (const float*)d_in[3];
    const float* W2 = (const float*)d_in[4];
    const float* b2 = (const float*)d_in[5];
    float*      out = (float*)d_out;

    static cudaStream_t sB = nullptr;          // created once; no device memory
    static cudaEvent_t  evFork = nullptr, evJoin = nullptr;
    if (sB == nullptr) {
        cudaStreamCreateWithFlags(&sB, cudaStreamNonBlocking);
        cudaEventCreateWithFlags(&evFork, cudaEventDisableTiming);
        cudaEventCreateWithFlags(&evJoin, cudaEventDisableTiming);
    }

    // fork: stream B joins the capture and runs the deg histogram
    cudaEventRecord(evFork, 0);
    cudaStreamWaitEvent(sB, evFork, 0);
    deg_kernel<<<(N_EDGES / 4 + 255) / 256, 256, 0, sB>>>(ei);
    cudaEventRecord(evJoin, sB);

    // stream 0: LUT + transpose (overlaps deg), then payload scatter
    init_kernel<<<TBL_BLOCKS + PREP_BLOCKS, 256>>>(mu, W1, b1, W2, b2);

    const long long lanes = (long long)N_EDGES * 2;
    edge_kernel<<<(int)((lanes + 255) / 256), 256>>>(ei);

    // join: mlp needs both deg (stream B) and agg (stream 0)
    cudaStreamWaitEvent(0, evJoin, 0);
    mlp_kernel<<<(N_NODES + 255) / 256, 256>>>(W1, b1, W2, b2, out);
}